// round 2
// baseline (speedup 1.0000x reference)
#include <cuda_runtime.h>

// OMul: r[i] = outer(x[i], y[i]) flattened.
// x: [N, 256] f32, y: [N, 256] f32, out: [N, 65536] f32.
// Pure store-bandwidth-bound: 1 GiB of output stores.
//
// One CTA per row: stage x/y row (2 KB) in smem, then 256 threads emit
// coalesced float4 streaming stores. Thread t covers float4-column (t & 63)
// for m = (t>>6) + 4*mi, mi = 0..63. Per warp: all lanes share one m
// (smem broadcast read) and write 32 consecutive float4 = 512 B contiguous.

static constexpr int M = 256;
static constexpr int K = 256;
static constexpr int THREADS = 256;

__global__ __launch_bounds__(THREADS, 8)
void omul_kernel(const float* __restrict__ x,
                 const float* __restrict__ y,
                 float* __restrict__ out)
{
    __shared__ float sx[M];
    __shared__ float sy[K];

    const int row = blockIdx.x;
    const int t   = threadIdx.x;

    sx[t] = x[(size_t)row * M + t];
    sy[t] = y[(size_t)row * K + t];
    __syncthreads();

    const int k4 = t & 63;        // which float4 chunk of k (0..63)
    const int m0 = t >> 6;        // 0..3: m offset within group of 4

    const float4 y4 = reinterpret_cast<const float4*>(sy)[k4];

    float4* out4 = reinterpret_cast<float4*>(out + (size_t)row * (M * K));

    #pragma unroll 8
    for (int mi = 0; mi < 64; mi++) {
        const int m = m0 + mi * 4;
        const float xv = sx[m];     // warp-uniform broadcast
        float4 v;
        v.x = xv * y4.x;
        v.y = xv * y4.y;
        v.z = xv * y4.z;
        v.w = xv * y4.w;
        // streaming store: output is 1 GiB, never re-read — bypass L2 residency
        __stcs(&out4[(size_t)m * 64 + k4], v);
    }
}

extern "C" void kernel_launch(void* const* d_in, const int* in_sizes, int n_in,
                              void* d_out, int out_size)
{
    const float* x = (const float*)d_in[0];
    const float* y = (const float*)d_in[1];
    float* out = (float*)d_out;

    const int n = in_sizes[0] / M;   // 4096 rows

    omul_kernel<<<n, THREADS>>>(x, y, out);
}